// round 8
// baseline (speedup 1.0000x reference)
#include <cuda_runtime.h>
#include <cstdint>

#define B_SZ  32
#define T_LEN 2048
#define I_DIM 128
#define H_DIM 256

// Scratch (allocation-free rule: __device__ globals)
__device__ __align__(256) float g_xB[B_SZ * T_LEN * H_DIM];  // 67 MB
__device__ __align__(256) float g_hs[B_SZ * T_LEN * H_DIM];  // 67 MB

// ---------------------------------------------------------------------------
// helpers
// ---------------------------------------------------------------------------
__device__ __forceinline__ uint32_t smem_u32(const void* p) {
    uint32_t a;
    asm("{ .reg .u64 t; cvta.to.shared.u64 t, %1; cvt.u32.u64 %0, t; }"
        : "=r"(a) : "l"(p));
    return a;
}

// packed fp32x2 FMA: full-rate FMA path on sm_103a (3-reg FFMA is half rate)
__device__ __forceinline__ void ffma2(unsigned long long& acc,
                                      unsigned long long a,
                                      unsigned long long b) {
    asm("fma.rn.f32x2 %0, %1, %2, %0;" : "+l"(acc) : "l"(a), "l"(b));
}
__device__ __forceinline__ unsigned long long pack2(float lo, float hi) {
    unsigned long long r;
    asm("mov.b64 %0, {%1, %2};" : "=l"(r) : "f"(lo), "f"(hi));
    return r;
}
__device__ __forceinline__ float2 unpack2(unsigned long long v) {
    float2 r;
    asm("mov.b64 {%0, %1}, %2;" : "=f"(r.x), "=f"(r.y) : "l"(v));
    return r;
}

// tanh(x) = 1 - 2/(exp(2x)+1), via MUFU.EX2 + MUFU.RCP.
// Abs err ~1e-7 (vs ~5e-4 for tanh.approx), chain ~40 cyc (vs ~100+ for tanhf).
// Saturates correctly: x->+inf: ex2->inf, rcp->0, result 1; x->-inf: result -1.
__device__ __forceinline__ float fast_tanh(float x) {
    float e, r;
    float t = x * 2.8853900817779268f;      // 2*log2(e)
    asm("ex2.approx.f32 %0, %1;" : "=f"(e) : "f"(t));
    float d = e + 1.0f;
    asm("rcp.approx.f32 %0, %1;" : "=f"(r) : "f"(d));
    return fmaf(-2.0f, r, 1.0f);
}

// ---------------------------------------------------------------------------
// Scan kernel: cluster of 2 CTAs per batch element.
//   CTA rank r owns output columns j in [128r, 128r+128).
//   256 threads: jj = tid&127 (output col), q = tid>>7 (k-half: 128 k each).
//   A column slices live in registers as packed f32x2 (64 ull regs/thread).
//
//   Per-step exchange (the R7 fix): q0 warps push their 128 new h values to
//   the peer CTA with st.async.shared::cluster.mbarrier::complete_tx::bytes
//   (4 warp-instructions total, data + tx-credit fused in HW). The consumer
//   posts ONE mbarrier.arrive.expect_tx(512B) per phase and parity-waits.
//   This replaces R6's 128 serialized remote mbarrier.arrive RMWs per step.
// ---------------------------------------------------------------------------
__global__ void __cluster_dims__(2, 1, 1) __launch_bounds__(256, 1)
scan_kernel(const float* __restrict__ A)
{
    __shared__ __align__(16) float h_s[2][H_DIM];   // double-buffered state
    __shared__ float scratch[128];                  // pair-reduce partials
    __shared__ __align__(8) unsigned long long mbar[1];

    const int tid   = threadIdx.x;
    const int jj    = tid & 127;
    const int q     = tid >> 7;            // 0 or 1 (k-half)
    uint32_t rank;
    asm("mov.u32 %0, %%cluster_ctarank;" : "=r"(rank));
    const int b     = blockIdx.x >> 1;
    const int j     = (int)rank * 128 + jj;   // global output column
    const int kbase = q * 128;

    // --- A slice -> registers, packed as (A[k][j], A[k+1][j]) pairs --------
    unsigned long long Ar[64];
#pragma unroll
    for (int m = 0; m < 64; m++) {
        float a0 = A[(size_t)(kbase + 2 * m)     * H_DIM + j];
        float a1 = A[(size_t)(kbase + 2 * m + 1) * H_DIM + j];
        Ar[m] = pack2(a0, a1);
    }

    // --- init shared state + mbarrier (count=1: the expect_tx arrival) -----
    h_s[0][tid] = 0.0f;          // tid covers 0..255 == H_DIM
    h_s[1][tid] = 0.0f;
    uint32_t mbar_a = smem_u32(mbar);
    if (tid == 0) {
        asm volatile("mbarrier.init.shared.b64 [%0], %1;"
                     :: "r"(mbar_a), "r"(1u) : "memory");
    }
    // cluster-wide visibility of init/zeros before any remote traffic
    asm volatile("barrier.cluster.arrive.aligned;" ::: "memory");
    asm volatile("barrier.cluster.wait.aligned;"   ::: "memory");

    // --- peer addresses (DSMEM) --------------------------------------------
    uint32_t peer = rank ^ 1u;
    uint32_t h0_a = smem_u32(&h_s[0][0]);
    uint32_t peer_h0, peer_mbar;
    asm("mapa.shared::cluster.u32 %0, %1, %2;" : "=r"(peer_h0)   : "r"(h0_a),   "r"(peer));
    asm("mapa.shared::cluster.u32 %0, %1, %2;" : "=r"(peer_mbar) : "r"(mbar_a), "r"(peer));

    // --- xB prefetch pipeline (distance 2 hides ~577cyc DRAM latency) ------
    const float* xb_base = g_xB + ((size_t)b * T_LEN) * H_DIM + j;
    float*       hs_out  = g_hs + ((size_t)b * T_LEN) * H_DIM + j;
    float xb_pre[2] = {0.0f, 0.0f};
    if (q == 0) {
        xb_pre[0] = __ldg(xb_base);
        xb_pre[1] = __ldg(xb_base + H_DIM);
    }

    // post expected-tx for phase 0 (512 bytes = peer's 128 floats)
    if (tid == 0) {
        asm volatile("mbarrier.arrive.expect_tx.shared::cta.b64 _, [%0], %1;"
                     :: "r"(mbar_a), "r"(512u) : "memory");
    }

    // --- main scan loop -----------------------------------------------------
    for (int t = 0; t < T_LEN; t++) {
        const int cur = t & 1;
        const int nxt = cur ^ 1;

        // dot over my 128 k values (smem h broadcast-read, A in regs)
        const ulonglong2* h2 =
            reinterpret_cast<const ulonglong2*>(&h_s[cur][kbase]);
        unsigned long long acc0 = 0ull, acc1 = 0ull;
#pragma unroll
        for (int m = 0; m < 32; m++) {
            ulonglong2 hv = h2[m];           // LDS.128: two packed f32x2
            ffma2(acc0, hv.x, Ar[2 * m]);
            ffma2(acc1, hv.y, Ar[2 * m + 1]);
        }
        float2 u0 = unpack2(acc0), u1 = unpack2(acc1);
        float partial = (u0.x + u0.y) + (u1.x + u1.y);

        if (q == 1) scratch[jj] = partial;
        __syncthreads();

        if (q == 0) {
            float tot = partial + scratch[jj] + xb_pre[t & 1];
            if (t + 2 < T_LEN)   // refill prefetch slot
                xb_pre[t & 1] = __ldg(xb_base + (size_t)(t + 2) * H_DIM);
            float hv = fast_tanh(tot);

            h_s[nxt][j] = hv;                              // local copy
            // fused remote store + tx-credit on the peer's mbarrier
            uint32_t ra = peer_h0 + (uint32_t)((nxt * H_DIM + j) * 4);
            asm volatile(
                "st.async.shared::cluster.mbarrier::complete_tx::bytes.b32 "
                "[%0], %1, [%2];"
                :: "r"(ra), "r"(__float_as_uint(hv)), "r"(peer_mbar)
                : "memory");
            hs_out[(size_t)t * H_DIM] = hv;                // for out-GEMM
        }
        __syncthreads();   // local h_s[nxt] half visible CTA-wide

        // wait for the peer's 512 bytes for this step (phase t, parity t&1)
        {
            uint32_t par = (uint32_t)(t & 1);
            asm volatile(
                "{\n\t.reg .pred P;\n"
                "W%=:\n\t"
                "mbarrier.try_wait.parity.acquire.cta.shared::cta.b64 P, [%0], %1, 0x989680;\n\t"
                "@!P bra W%=;\n\t"
                "}"
                :: "r"(mbar_a), "r"(par) : "memory");
        }
        // post expected-tx for the next phase (harmless extra at t=T-1)
        if (tid == 0) {
            asm volatile("mbarrier.arrive.expect_tx.shared::cta.b64 _, [%0], %1;"
                         :: "r"(mbar_a), "r"(512u) : "memory");
        }
    }

    asm volatile("barrier.cluster.arrive.aligned;" ::: "memory");
    asm volatile("barrier.cluster.wait.aligned;"   ::: "memory");
}

// ---------------------------------------------------------------------------
// fp32 tiled GEMM: C[M,N] = A[M,K] @ B[K,N], all row-major.
// 128x128 block tile, k-tile 16, 256 threads, 8x8 microtile.
// Accumulators are packed f32x2 (fma.rn.f32x2) -> full-rate FMA pipe.
// Assumes M%128==0, N%128==0, K%16==0 (holds for all three uses).
// (Measured ~90% of the fp32 FMA roofline in R7 — left unchanged.)
// ---------------------------------------------------------------------------
__global__ void __launch_bounds__(256)
gemm_f32(const float* __restrict__ Ag, const float* __restrict__ Bg,
         float* __restrict__ Cg, int M, int N, int K)
{
    __shared__ __align__(16) float As[16][128];   // transposed A tile
    __shared__ __align__(16) float Bs[16][128];

    const int tid = threadIdx.x;
    const int bm  = blockIdx.x * 128;
    const int bn  = blockIdx.y * 128;
    const int tx  = tid & 15;     // n direction
    const int ty  = tid >> 4;     // m direction
    const int m0  = ty * 8;
    const int n0  = tx * 8;

    unsigned long long acc[8][4];
#pragma unroll
    for (int i = 0; i < 8; i++)
#pragma unroll
        for (int p = 0; p < 4; p++) acc[i][p] = 0ull;

    for (int k0 = 0; k0 < K; k0 += 16) {
        // load A tile (128 rows x 16 cols), store transposed
#pragma unroll
        for (int l = 0; l < 2; l++) {
            int v  = tid + l * 256;
            int r  = v >> 2;
            int c4 = v & 3;
            float4 a = *reinterpret_cast<const float4*>(
                &Ag[(size_t)(bm + r) * K + k0 + c4 * 4]);
            As[c4 * 4 + 0][r] = a.x;
            As[c4 * 4 + 1][r] = a.y;
            As[c4 * 4 + 2][r] = a.z;
            As[c4 * 4 + 3][r] = a.w;
        }
        // load B tile (16 rows x 128 cols)
#pragma unroll
        for (int l = 0; l < 2; l++) {
            int v  = tid + l * 256;
            int kk = v >> 5;
            int c4 = v & 31;
            *reinterpret_cast<float4*>(&Bs[kk][c4 * 4]) =
                *reinterpret_cast<const float4*>(
                    &Bg[(size_t)(k0 + kk) * N + bn + c4 * 4]);
        }
        __syncthreads();

#pragma unroll
        for (int kk = 0; kk < 16; kk++) {
            float4 a0 = *reinterpret_cast<const float4*>(&As[kk][m0]);
            float4 a1 = *reinterpret_cast<const float4*>(&As[kk][m0 + 4]);
            ulonglong2 b0 = *reinterpret_cast<const ulonglong2*>(&Bs[kk][n0]);
            ulonglong2 b1 = *reinterpret_cast<const ulonglong2*>(&Bs[kk][n0 + 4]);

            unsigned long long ap[8];
            ap[0] = pack2(a0.x, a0.x); ap[1] = pack2(a0.y, a0.y);
            ap[2] = pack2(a0.z, a0.z); ap[3] = pack2(a0.w, a0.w);
            ap[4] = pack2(a1.x, a1.x); ap[5] = pack2(a1.y, a1.y);
            ap[6] = pack2(a1.z, a1.z); ap[7] = pack2(a1.w, a1.w);
            unsigned long long bv0 = b0.x, bv1 = b0.y, bv2 = b1.x, bv3 = b1.y;

#pragma unroll
            for (int i = 0; i < 8; i++) {
                ffma2(acc[i][0], ap[i], bv0);
                ffma2(acc[i][1], ap[i], bv1);
                ffma2(acc[i][2], ap[i], bv2);
                ffma2(acc[i][3], ap[i], bv3);
            }
        }
        __syncthreads();
    }

    // epilogue
#pragma unroll
    for (int i = 0; i < 8; i++) {
        float o[8];
#pragma unroll
        for (int p = 0; p < 4; p++) {
            float2 u = unpack2(acc[i][p]);
            o[2 * p] = u.x; o[2 * p + 1] = u.y;
        }
        float4* dst = reinterpret_cast<float4*>(
            &Cg[(size_t)(bm + m0 + i) * N + bn + n0]);
        dst[0] = make_float4(o[0], o[1], o[2], o[3]);
        dst[1] = make_float4(o[4], o[5], o[6], o[7]);
    }
}

// ---------------------------------------------------------------------------
// launch
// ---------------------------------------------------------------------------
extern "C" void kernel_launch(void* const* d_in, const int* in_sizes, int n_in,
                              void* d_out, int out_size)
{
    (void)in_sizes; (void)n_in; (void)out_size;
    const float* x  = (const float*)d_in[0];   // [32, 2048, 128]
    const float* A  = (const float*)d_in[1];   // [256, 256]
    const float* Bm = (const float*)d_in[2];   // [128, 256]
    const float* C  = (const float*)d_in[3];   // [256, 256]
    float* out = (float*)d_out;                // [32, 2048, 256]

    float* xB = nullptr;
    float* hs = nullptr;
    cudaGetSymbolAddress((void**)&xB, g_xB);   // pure query: capture-safe
    cudaGetSymbolAddress((void**)&hs, g_hs);

    const int M = B_SZ * T_LEN;                // 65536

    // 1) xB = x @ Bm   (M x 128) @ (128 x 256)
    gemm_f32<<<dim3(M / 128, H_DIM / 128), 256>>>(x, Bm, xB, M, H_DIM, I_DIM);
    // 2) sequential tanh scan, 32 clusters of 2 CTAs
    scan_kernel<<<B_SZ * 2, 256>>>(A);
    // 3) out = hs @ C  (M x 256) @ (256 x 256)
    gemm_f32<<<dim3(M / 128, H_DIM / 128), 256>>>(hs, C, out, M, H_DIM, H_DIM);
}

// round 9
// speedup vs baseline: 1.4508x; 1.4508x over previous
#include <cuda_runtime.h>
#include <cstdint>

#define B_SZ  32
#define T_LEN 2048
#define I_DIM 128
#define H_DIM 256

// Scratch (allocation-free rule: __device__ globals)
__device__ __align__(256) float g_xB[B_SZ * T_LEN * H_DIM];  // 67 MB
__device__ __align__(256) float g_hs[B_SZ * T_LEN * H_DIM];  // 67 MB

// ---------------------------------------------------------------------------
// helpers
// ---------------------------------------------------------------------------
__device__ __forceinline__ uint32_t smem_u32(const void* p) {
    uint32_t a;
    asm("{ .reg .u64 t; cvta.to.shared.u64 t, %1; cvt.u32.u64 %0, t; }"
        : "=r"(a) : "l"(p));
    return a;
}

// packed fp32x2 FMA: full-rate FMA path on sm_103a (3-reg FFMA is half rate)
__device__ __forceinline__ void ffma2(unsigned long long& acc,
                                      unsigned long long a,
                                      unsigned long long b) {
    asm("fma.rn.f32x2 %0, %1, %2, %0;" : "+l"(acc) : "l"(a), "l"(b));
}
__device__ __forceinline__ unsigned long long pack2(float lo, float hi) {
    unsigned long long r;
    asm("mov.b64 %0, {%1, %2};" : "=l"(r) : "f"(lo), "f"(hi));
    return r;
}
__device__ __forceinline__ float2 unpack2(unsigned long long v) {
    float2 r;
    asm("mov.b64 {%0, %1}, %2;" : "=f"(r.x), "=f"(r.y) : "l"(v));
    return r;
}

// tanh(x) = 1 - 2/(exp(2x)+1), via MUFU.EX2 + MUFU.RCP.
// Abs err ~1e-7 (vs ~5e-4 for tanh.approx), chain ~40 cyc (vs ~100+ for tanhf).
// Saturates correctly: x->+inf: ex2->inf, rcp->0, result 1; x->-inf: result -1.
__device__ __forceinline__ float fast_tanh(float x) {
    float e, r;
    float t = x * 2.8853900817779268f;      // 2*log2(e)
    asm("ex2.approx.f32 %0, %1;" : "=f"(e) : "f"(t));
    float d = e + 1.0f;
    asm("rcp.approx.f32 %0, %1;" : "=f"(r) : "f"(d));
    return fmaf(-2.0f, r, 1.0f);
}

// ---------------------------------------------------------------------------
// Scan kernel: cluster of 2 CTAs per batch element.
//   CTA rank r owns output columns j in [128r, 128r+128).
//   256 threads: jj = tid&127 (output col), q = tid>>7 (k-half: 128 k each).
//   A column slices live in registers as packed f32x2 (64 ull regs/thread).
//
//   Per-step exchange (the R7 fix): q0 warps push their 128 new h values to
//   the peer CTA with st.async.shared::cluster.mbarrier::complete_tx::bytes
//   (4 warp-instructions total, data + tx-credit fused in HW). The consumer
//   posts ONE mbarrier.arrive.expect_tx(512B) per phase and parity-waits.
//   This replaces R6's 128 serialized remote mbarrier.arrive RMWs per step.
// ---------------------------------------------------------------------------
__global__ void __cluster_dims__(2, 1, 1) __launch_bounds__(256, 1)
scan_kernel(const float* __restrict__ A)
{
    __shared__ __align__(16) float h_s[2][H_DIM];   // double-buffered state
    __shared__ float scratch[128];                  // pair-reduce partials
    __shared__ __align__(8) unsigned long long mbar[1];

    const int tid   = threadIdx.x;
    const int jj    = tid & 127;
    const int q     = tid >> 7;            // 0 or 1 (k-half)
    uint32_t rank;
    asm("mov.u32 %0, %%cluster_ctarank;" : "=r"(rank));
    const int b     = blockIdx.x >> 1;
    const int j     = (int)rank * 128 + jj;   // global output column
    const int kbase = q * 128;

    // --- A slice -> registers, packed as (A[k][j], A[k+1][j]) pairs --------
    unsigned long long Ar[64];
#pragma unroll
    for (int m = 0; m < 64; m++) {
        float a0 = A[(size_t)(kbase + 2 * m)     * H_DIM + j];
        float a1 = A[(size_t)(kbase + 2 * m + 1) * H_DIM + j];
        Ar[m] = pack2(a0, a1);
    }

    // --- init shared state + mbarrier (count=1: the expect_tx arrival) -----
    h_s[0][tid] = 0.0f;          // tid covers 0..255 == H_DIM
    h_s[1][tid] = 0.0f;
    uint32_t mbar_a = smem_u32(mbar);
    if (tid == 0) {
        asm volatile("mbarrier.init.shared.b64 [%0], %1;"
                     :: "r"(mbar_a), "r"(1u) : "memory");
    }
    // cluster-wide visibility of init/zeros before any remote traffic
    asm volatile("barrier.cluster.arrive.aligned;" ::: "memory");
    asm volatile("barrier.cluster.wait.aligned;"   ::: "memory");

    // --- peer addresses (DSMEM) --------------------------------------------
    uint32_t peer = rank ^ 1u;
    uint32_t h0_a = smem_u32(&h_s[0][0]);
    uint32_t peer_h0, peer_mbar;
    asm("mapa.shared::cluster.u32 %0, %1, %2;" : "=r"(peer_h0)   : "r"(h0_a),   "r"(peer));
    asm("mapa.shared::cluster.u32 %0, %1, %2;" : "=r"(peer_mbar) : "r"(mbar_a), "r"(peer));

    // --- xB prefetch pipeline (distance 2 hides ~577cyc DRAM latency) ------
    const float* xb_base = g_xB + ((size_t)b * T_LEN) * H_DIM + j;
    float*       hs_out  = g_hs + ((size_t)b * T_LEN) * H_DIM + j;
    float xb_pre[2] = {0.0f, 0.0f};
    if (q == 0) {
        xb_pre[0] = __ldg(xb_base);
        xb_pre[1] = __ldg(xb_base + H_DIM);
    }

    // post expected-tx for phase 0 (512 bytes = peer's 128 floats)
    if (tid == 0) {
        asm volatile("mbarrier.arrive.expect_tx.shared::cta.b64 _, [%0], %1;"
                     :: "r"(mbar_a), "r"(512u) : "memory");
    }

    // --- main scan loop -----------------------------------------------------
    for (int t = 0; t < T_LEN; t++) {
        const int cur = t & 1;
        const int nxt = cur ^ 1;

        // dot over my 128 k values (smem h broadcast-read, A in regs)
        const ulonglong2* h2 =
            reinterpret_cast<const ulonglong2*>(&h_s[cur][kbase]);
        unsigned long long acc0 = 0ull, acc1 = 0ull;
#pragma unroll
        for (int m = 0; m < 32; m++) {
            ulonglong2 hv = h2[m];           // LDS.128: two packed f32x2
            ffma2(acc0, hv.x, Ar[2 * m]);
            ffma2(acc1, hv.y, Ar[2 * m + 1]);
        }
        float2 u0 = unpack2(acc0), u1 = unpack2(acc1);
        float partial = (u0.x + u0.y) + (u1.x + u1.y);

        if (q == 1) scratch[jj] = partial;
        __syncthreads();

        if (q == 0) {
            float tot = partial + scratch[jj] + xb_pre[t & 1];
            if (t + 2 < T_LEN)   // refill prefetch slot
                xb_pre[t & 1] = __ldg(xb_base + (size_t)(t + 2) * H_DIM);
            float hv = fast_tanh(tot);

            h_s[nxt][j] = hv;                              // local copy
            // fused remote store + tx-credit on the peer's mbarrier
            uint32_t ra = peer_h0 + (uint32_t)((nxt * H_DIM + j) * 4);
            asm volatile(
                "st.async.shared::cluster.mbarrier::complete_tx::bytes.b32 "
                "[%0], %1, [%2];"
                :: "r"(ra), "r"(__float_as_uint(hv)), "r"(peer_mbar)
                : "memory");
            hs_out[(size_t)t * H_DIM] = hv;                // for out-GEMM
        }
        __syncthreads();   // local h_s[nxt] half visible CTA-wide

        // wait for the peer's 512 bytes for this step (phase t, parity t&1)
        {
            uint32_t par = (uint32_t)(t & 1);
            asm volatile(
                "{\n\t.reg .pred P;\n"
                "W%=:\n\t"
                "mbarrier.try_wait.parity.acquire.cta.shared::cta.b64 P, [%0], %1, 0x989680;\n\t"
                "@!P bra W%=;\n\t"
                "}"
                :: "r"(mbar_a), "r"(par) : "memory");
        }
        // post expected-tx for the next phase (harmless extra at t=T-1)
        if (tid == 0) {
            asm volatile("mbarrier.arrive.expect_tx.shared::cta.b64 _, [%0], %1;"
                         :: "r"(mbar_a), "r"(512u) : "memory");
        }
    }

    asm volatile("barrier.cluster.arrive.aligned;" ::: "memory");
    asm volatile("barrier.cluster.wait.aligned;"   ::: "memory");
}

// ---------------------------------------------------------------------------
// fp32 tiled GEMM: C[M,N] = A[M,K] @ B[K,N], all row-major.
// 128x128 block tile, k-tile 16, 256 threads, 8x8 microtile.
// Accumulators are packed f32x2 (fma.rn.f32x2) -> full-rate FMA pipe.
// Assumes M%128==0, N%128==0, K%16==0 (holds for all three uses).
// (Measured ~90% of the fp32 FMA roofline in R7 — left unchanged.)
// ---------------------------------------------------------------------------
__global__ void __launch_bounds__(256)
gemm_f32(const float* __restrict__ Ag, const float* __restrict__ Bg,
         float* __restrict__ Cg, int M, int N, int K)
{
    __shared__ __align__(16) float As[16][128];   // transposed A tile
    __shared__ __align__(16) float Bs[16][128];

    const int tid = threadIdx.x;
    const int bm  = blockIdx.x * 128;
    const int bn  = blockIdx.y * 128;
    const int tx  = tid & 15;     // n direction
    const int ty  = tid >> 4;     // m direction
    const int m0  = ty * 8;
    const int n0  = tx * 8;

    unsigned long long acc[8][4];
#pragma unroll
    for (int i = 0; i < 8; i++)
#pragma unroll
        for (int p = 0; p < 4; p++) acc[i][p] = 0ull;

    for (int k0 = 0; k0 < K; k0 += 16) {
        // load A tile (128 rows x 16 cols), store transposed
#pragma unroll
        for (int l = 0; l < 2; l++) {
            int v  = tid + l * 256;
            int r  = v >> 2;
            int c4 = v & 3;
            float4 a = *reinterpret_cast<const float4*>(
                &Ag[(size_t)(bm + r) * K + k0 + c4 * 4]);
            As[c4 * 4 + 0][r] = a.x;
            As[c4 * 4 + 1][r] = a.y;
            As[c4 * 4 + 2][r] = a.z;
            As[c4 * 4 + 3][r] = a.w;
        }
        // load B tile (16 rows x 128 cols)
#pragma unroll
        for (int l = 0; l < 2; l++) {
            int v  = tid + l * 256;
            int kk = v >> 5;
            int c4 = v & 31;
            *reinterpret_cast<float4*>(&Bs[kk][c4 * 4]) =
                *reinterpret_cast<const float4*>(
                    &Bg[(size_t)(k0 + kk) * N + bn + c4 * 4]);
        }
        __syncthreads();

#pragma unroll
        for (int kk = 0; kk < 16; kk++) {
            float4 a0 = *reinterpret_cast<const float4*>(&As[kk][m0]);
            float4 a1 = *reinterpret_cast<const float4*>(&As[kk][m0 + 4]);
            ulonglong2 b0 = *reinterpret_cast<const ulonglong2*>(&Bs[kk][n0]);
            ulonglong2 b1 = *reinterpret_cast<const ulonglong2*>(&Bs[kk][n0 + 4]);

            unsigned long long ap[8];
            ap[0] = pack2(a0.x, a0.x); ap[1] = pack2(a0.y, a0.y);
            ap[2] = pack2(a0.z, a0.z); ap[3] = pack2(a0.w, a0.w);
            ap[4] = pack2(a1.x, a1.x); ap[5] = pack2(a1.y, a1.y);
            ap[6] = pack2(a1.z, a1.z); ap[7] = pack2(a1.w, a1.w);
            unsigned long long bv0 = b0.x, bv1 = b0.y, bv2 = b1.x, bv3 = b1.y;

#pragma unroll
            for (int i = 0; i < 8; i++) {
                ffma2(acc[i][0], ap[i], bv0);
                ffma2(acc[i][1], ap[i], bv1);
                ffma2(acc[i][2], ap[i], bv2);
                ffma2(acc[i][3], ap[i], bv3);
            }
        }
        __syncthreads();
    }

    // epilogue
#pragma unroll
    for (int i = 0; i < 8; i++) {
        float o[8];
#pragma unroll
        for (int p = 0; p < 4; p++) {
            float2 u = unpack2(acc[i][p]);
            o[2 * p] = u.x; o[2 * p + 1] = u.y;
        }
        float4* dst = reinterpret_cast<float4*>(
            &Cg[(size_t)(bm + m0 + i) * N + bn + n0]);
        dst[0] = make_float4(o[0], o[1], o[2], o[3]);
        dst[1] = make_float4(o[4], o[5], o[6], o[7]);
    }
}

// ---------------------------------------------------------------------------
// launch
// ---------------------------------------------------------------------------
extern "C" void kernel_launch(void* const* d_in, const int* in_sizes, int n_in,
                              void* d_out, int out_size)
{
    (void)in_sizes; (void)n_in; (void)out_size;
    const float* x  = (const float*)d_in[0];   // [32, 2048, 128]
    const float* A  = (const float*)d_in[1];   // [256, 256]
    const float* Bm = (const float*)d_in[2];   // [128, 256]
    const float* C  = (const float*)d_in[3];   // [256, 256]
    float* out = (float*)d_out;                // [32, 2048, 256]

    float* xB = nullptr;
    float* hs = nullptr;
    cudaGetSymbolAddress((void**)&xB, g_xB);   // pure query: capture-safe
    cudaGetSymbolAddress((void**)&hs, g_hs);

    const int M = B_SZ * T_LEN;                // 65536

    // 1) xB = x @ Bm   (M x 128) @ (128 x 256)
    gemm_f32<<<dim3(M / 128, H_DIM / 128), 256>>>(x, Bm, xB, M, H_DIM, I_DIM);
    // 2) sequential tanh scan, 32 clusters of 2 CTAs
    scan_kernel<<<B_SZ * 2, 256>>>(A);
    // 3) out = hs @ C  (M x 256) @ (256 x 256)
    gemm_f32<<<dim3(M / 128, H_DIM / 128), 256>>>(hs, C, out, M, H_DIM, H_DIM);
}

// round 10
// speedup vs baseline: 1.4618x; 1.0076x over previous
#include <cuda_runtime.h>
#include <cstdint>

#define B_SZ  32
#define T_LEN 2048
#define I_DIM 128
#define H_DIM 256

// Scratch (allocation-free rule: __device__ globals)
__device__ __align__(256) float g_xB[B_SZ * T_LEN * H_DIM];  // 67 MB
__device__ __align__(256) float g_hs[B_SZ * T_LEN * H_DIM];  // 67 MB

// ---------------------------------------------------------------------------
// helpers
// ---------------------------------------------------------------------------
__device__ __forceinline__ uint32_t smem_u32(const void* p) {
    uint32_t a;
    asm("{ .reg .u64 t; cvta.to.shared.u64 t, %1; cvt.u32.u64 %0, t; }"
        : "=r"(a) : "l"(p));
    return a;
}

// packed fp32x2 FMA: full-rate FMA path on sm_103a (3-reg FFMA is half rate)
__device__ __forceinline__ void ffma2(unsigned long long& acc,
                                      unsigned long long a,
                                      unsigned long long b) {
    asm("fma.rn.f32x2 %0, %1, %2, %0;" : "+l"(acc) : "l"(a), "l"(b));
}
__device__ __forceinline__ unsigned long long pack2(float lo, float hi) {
    unsigned long long r;
    asm("mov.b64 %0, {%1, %2};" : "=l"(r) : "f"(lo), "f"(hi));
    return r;
}
__device__ __forceinline__ float2 unpack2(unsigned long long v) {
    float2 r;
    asm("mov.b64 {%0, %1}, %2;" : "=f"(r.x), "=f"(r.y) : "l"(v));
    return r;
}

// tanh(x) = 1 - 2/(exp(2x)+1), via MUFU.EX2 + MUFU.RCP.
// Abs err ~1e-7 (vs ~5e-4 for tanh.approx), chain ~40 cyc (vs ~100+ for tanhf).
// Saturates correctly: x->+inf: ex2->inf, rcp->0, result 1; x->-inf: result -1.
__device__ __forceinline__ float fast_tanh(float x) {
    float e, r;
    float t = x * 2.8853900817779268f;      // 2*log2(e)
    asm("ex2.approx.f32 %0, %1;" : "=f"(e) : "f"(t));
    float d = e + 1.0f;
    asm("rcp.approx.f32 %0, %1;" : "=f"(r) : "f"(d));
    return fmaf(-2.0f, r, 1.0f);
}

// ---------------------------------------------------------------------------
// Scan kernel: cluster of 2 CTAs per batch element.
//   CTA rank r owns output columns j in [128r, 128r+128).
//   256 threads: jj = tid&127 (output col), q = tid>>7 (k-half: 128 k each).
//   A column slices live in registers as packed f32x2 (64 ull regs/thread).
//
//   Per-step exchange (the R7 fix): q0 warps push their 128 new h values to
//   the peer CTA with st.async.shared::cluster.mbarrier::complete_tx::bytes
//   (4 warp-instructions total, data + tx-credit fused in HW). The consumer
//   posts ONE mbarrier.arrive.expect_tx(512B) per phase and parity-waits.
//   This replaces R6's 128 serialized remote mbarrier.arrive RMWs per step.
// ---------------------------------------------------------------------------
__global__ void __cluster_dims__(2, 1, 1) __launch_bounds__(256, 1)
scan_kernel(const float* __restrict__ A)
{
    __shared__ __align__(16) float h_s[2][H_DIM];   // double-buffered state
    __shared__ float scratch[128];                  // pair-reduce partials
    __shared__ __align__(8) unsigned long long mbar[1];

    const int tid   = threadIdx.x;
    const int jj    = tid & 127;
    const int q     = tid >> 7;            // 0 or 1 (k-half)
    uint32_t rank;
    asm("mov.u32 %0, %%cluster_ctarank;" : "=r"(rank));
    const int b     = blockIdx.x >> 1;
    const int j     = (int)rank * 128 + jj;   // global output column
    const int kbase = q * 128;

    // --- A slice -> registers, packed as (A[k][j], A[k+1][j]) pairs --------
    unsigned long long Ar[64];
#pragma unroll
    for (int m = 0; m < 64; m++) {
        float a0 = A[(size_t)(kbase + 2 * m)     * H_DIM + j];
        float a1 = A[(size_t)(kbase + 2 * m + 1) * H_DIM + j];
        Ar[m] = pack2(a0, a1);
    }

    // --- init shared state + mbarrier (count=1: the expect_tx arrival) -----
    h_s[0][tid] = 0.0f;          // tid covers 0..255 == H_DIM
    h_s[1][tid] = 0.0f;
    uint32_t mbar_a = smem_u32(mbar);
    if (tid == 0) {
        asm volatile("mbarrier.init.shared.b64 [%0], %1;"
                     :: "r"(mbar_a), "r"(1u) : "memory");
    }
    // cluster-wide visibility of init/zeros before any remote traffic
    asm volatile("barrier.cluster.arrive.aligned;" ::: "memory");
    asm volatile("barrier.cluster.wait.aligned;"   ::: "memory");

    // --- peer addresses (DSMEM) --------------------------------------------
    uint32_t peer = rank ^ 1u;
    uint32_t h0_a = smem_u32(&h_s[0][0]);
    uint32_t peer_h0, peer_mbar;
    asm("mapa.shared::cluster.u32 %0, %1, %2;" : "=r"(peer_h0)   : "r"(h0_a),   "r"(peer));
    asm("mapa.shared::cluster.u32 %0, %1, %2;" : "=r"(peer_mbar) : "r"(mbar_a), "r"(peer));

    // --- xB prefetch pipeline (distance 2 hides ~577cyc DRAM latency) ------
    const float* xb_base = g_xB + ((size_t)b * T_LEN) * H_DIM + j;
    float*       hs_out  = g_hs + ((size_t)b * T_LEN) * H_DIM + j;
    float xb_pre[2] = {0.0f, 0.0f};
    if (q == 0) {
        xb_pre[0] = __ldg(xb_base);
        xb_pre[1] = __ldg(xb_base + H_DIM);
    }

    // post expected-tx for phase 0 (512 bytes = peer's 128 floats)
    if (tid == 0) {
        asm volatile("mbarrier.arrive.expect_tx.shared::cta.b64 _, [%0], %1;"
                     :: "r"(mbar_a), "r"(512u) : "memory");
    }

    // --- main scan loop -----------------------------------------------------
    for (int t = 0; t < T_LEN; t++) {
        const int cur = t & 1;
        const int nxt = cur ^ 1;

        // dot over my 128 k values (smem h broadcast-read, A in regs)
        const ulonglong2* h2 =
            reinterpret_cast<const ulonglong2*>(&h_s[cur][kbase]);
        unsigned long long acc0 = 0ull, acc1 = 0ull;
#pragma unroll
        for (int m = 0; m < 32; m++) {
            ulonglong2 hv = h2[m];           // LDS.128: two packed f32x2
            ffma2(acc0, hv.x, Ar[2 * m]);
            ffma2(acc1, hv.y, Ar[2 * m + 1]);
        }
        float2 u0 = unpack2(acc0), u1 = unpack2(acc1);
        float partial = (u0.x + u0.y) + (u1.x + u1.y);

        if (q == 1) scratch[jj] = partial;
        __syncthreads();

        if (q == 0) {
            float tot = partial + scratch[jj] + xb_pre[t & 1];
            if (t + 2 < T_LEN)   // refill prefetch slot
                xb_pre[t & 1] = __ldg(xb_base + (size_t)(t + 2) * H_DIM);
            float hv = fast_tanh(tot);

            h_s[nxt][j] = hv;                              // local copy
            // fused remote store + tx-credit on the peer's mbarrier
            uint32_t ra = peer_h0 + (uint32_t)((nxt * H_DIM + j) * 4);
            asm volatile(
                "st.async.shared::cluster.mbarrier::complete_tx::bytes.b32 "
                "[%0], %1, [%2];"
                :: "r"(ra), "r"(__float_as_uint(hv)), "r"(peer_mbar)
                : "memory");
            hs_out[(size_t)t * H_DIM] = hv;                // for out-GEMM
        }
        __syncthreads();   // local h_s[nxt] half visible CTA-wide

        // wait for the peer's 512 bytes for this step (phase t, parity t&1)
        {
            uint32_t par = (uint32_t)(t & 1);
            asm volatile(
                "{\n\t.reg .pred P;\n"
                "W%=:\n\t"
                "mbarrier.try_wait.parity.acquire.cta.shared::cta.b64 P, [%0], %1, 0x989680;\n\t"
                "@!P bra W%=;\n\t"
                "}"
                :: "r"(mbar_a), "r"(par) : "memory");
        }
        // post expected-tx for the next phase (harmless extra at t=T-1)
        if (tid == 0) {
            asm volatile("mbarrier.arrive.expect_tx.shared::cta.b64 _, [%0], %1;"
                         :: "r"(mbar_a), "r"(512u) : "memory");
        }
    }

    asm volatile("barrier.cluster.arrive.aligned;" ::: "memory");
    asm volatile("barrier.cluster.wait.aligned;"   ::: "memory");
}

// ---------------------------------------------------------------------------
// fp32 tiled GEMM: C[M,N] = A[M,K] @ B[K,N], all row-major.
// 128x128 block tile, k-tile 16, 256 threads, 8x8 microtile.
// Accumulators are packed f32x2 (fma.rn.f32x2) -> full-rate FMA pipe.
// Assumes M%128==0, N%128==0, K%16==0 (holds for all three uses).
// (Measured ~90% of the fp32 FMA roofline in R7 — left unchanged.)
// ---------------------------------------------------------------------------
__global__ void __launch_bounds__(256)
gemm_f32(const float* __restrict__ Ag, const float* __restrict__ Bg,
         float* __restrict__ Cg, int M, int N, int K)
{
    __shared__ __align__(16) float As[16][128];   // transposed A tile
    __shared__ __align__(16) float Bs[16][128];

    const int tid = threadIdx.x;
    const int bm  = blockIdx.x * 128;
    const int bn  = blockIdx.y * 128;
    const int tx  = tid & 15;     // n direction
    const int ty  = tid >> 4;     // m direction
    const int m0  = ty * 8;
    const int n0  = tx * 8;

    unsigned long long acc[8][4];
#pragma unroll
    for (int i = 0; i < 8; i++)
#pragma unroll
        for (int p = 0; p < 4; p++) acc[i][p] = 0ull;

    for (int k0 = 0; k0 < K; k0 += 16) {
        // load A tile (128 rows x 16 cols), store transposed
#pragma unroll
        for (int l = 0; l < 2; l++) {
            int v  = tid + l * 256;
            int r  = v >> 2;
            int c4 = v & 3;
            float4 a = *reinterpret_cast<const float4*>(
                &Ag[(size_t)(bm + r) * K + k0 + c4 * 4]);
            As[c4 * 4 + 0][r] = a.x;
            As[c4 * 4 + 1][r] = a.y;
            As[c4 * 4 + 2][r] = a.z;
            As[c4 * 4 + 3][r] = a.w;
        }
        // load B tile (16 rows x 128 cols)
#pragma unroll
        for (int l = 0; l < 2; l++) {
            int v  = tid + l * 256;
            int kk = v >> 5;
            int c4 = v & 31;
            *reinterpret_cast<float4*>(&Bs[kk][c4 * 4]) =
                *reinterpret_cast<const float4*>(
                    &Bg[(size_t)(k0 + kk) * N + bn + c4 * 4]);
        }
        __syncthreads();

#pragma unroll
        for (int kk = 0; kk < 16; kk++) {
            float4 a0 = *reinterpret_cast<const float4*>(&As[kk][m0]);
            float4 a1 = *reinterpret_cast<const float4*>(&As[kk][m0 + 4]);
            ulonglong2 b0 = *reinterpret_cast<const ulonglong2*>(&Bs[kk][n0]);
            ulonglong2 b1 = *reinterpret_cast<const ulonglong2*>(&Bs[kk][n0 + 4]);

            unsigned long long ap[8];
            ap[0] = pack2(a0.x, a0.x); ap[1] = pack2(a0.y, a0.y);
            ap[2] = pack2(a0.z, a0.z); ap[3] = pack2(a0.w, a0.w);
            ap[4] = pack2(a1.x, a1.x); ap[5] = pack2(a1.y, a1.y);
            ap[6] = pack2(a1.z, a1.z); ap[7] = pack2(a1.w, a1.w);
            unsigned long long bv0 = b0.x, bv1 = b0.y, bv2 = b1.x, bv3 = b1.y;

#pragma unroll
            for (int i = 0; i < 8; i++) {
                ffma2(acc[i][0], ap[i], bv0);
                ffma2(acc[i][1], ap[i], bv1);
                ffma2(acc[i][2], ap[i], bv2);
                ffma2(acc[i][3], ap[i], bv3);
            }
        }
        __syncthreads();
    }

    // epilogue
#pragma unroll
    for (int i = 0; i < 8; i++) {
        float o[8];
#pragma unroll
        for (int p = 0; p < 4; p++) {
            float2 u = unpack2(acc[i][p]);
            o[2 * p] = u.x; o[2 * p + 1] = u.y;
        }
        float4* dst = reinterpret_cast<float4*>(
            &Cg[(size_t)(bm + m0 + i) * N + bn + n0]);
        dst[0] = make_float4(o[0], o[1], o[2], o[3]);
        dst[1] = make_float4(o[4], o[5], o[6], o[7]);
    }
}

// ---------------------------------------------------------------------------
// launch
// ---------------------------------------------------------------------------
extern "C" void kernel_launch(void* const* d_in, const int* in_sizes, int n_in,
                              void* d_out, int out_size)
{
    (void)in_sizes; (void)n_in; (void)out_size;
    const float* x  = (const float*)d_in[0];   // [32, 2048, 128]
    const float* A  = (const float*)d_in[1];   // [256, 256]
    const float* Bm = (const float*)d_in[2];   // [128, 256]
    const float* C  = (const float*)d_in[3];   // [256, 256]
    float* out = (float*)d_out;                // [32, 2048, 256]

    float* xB = nullptr;
    float* hs = nullptr;
    cudaGetSymbolAddress((void**)&xB, g_xB);   // pure query: capture-safe
    cudaGetSymbolAddress((void**)&hs, g_hs);

    const int M = B_SZ * T_LEN;                // 65536

    // 1) xB = x @ Bm   (M x 128) @ (128 x 256)
    gemm_f32<<<dim3(M / 128, H_DIM / 128), 256>>>(x, Bm, xB, M, H_DIM, I_DIM);
    // 2) sequential tanh scan, 32 clusters of 2 CTAs
    scan_kernel<<<B_SZ * 2, 256>>>(A);
    // 3) out = hs @ C  (M x 256) @ (256 x 256)
    gemm_f32<<<dim3(M / 128, H_DIM / 128), 256>>>(hs, C, out, M, H_DIM, H_DIM);
}

// round 11
// speedup vs baseline: 1.4828x; 1.0144x over previous
#include <cuda_runtime.h>
#include <cstdint>

#define B_SZ  32
#define T_LEN 2048
#define I_DIM 128
#define H_DIM 256

// Scratch (allocation-free rule: __device__ globals)
__device__ __align__(256) float g_xB[B_SZ * T_LEN * H_DIM];  // 67 MB
__device__ __align__(256) float g_hs[B_SZ * T_LEN * H_DIM];  // 67 MB

// ---------------------------------------------------------------------------
// helpers
// ---------------------------------------------------------------------------
__device__ __forceinline__ uint32_t smem_u32(const void* p) {
    uint32_t a;
    asm("{ .reg .u64 t; cvta.to.shared.u64 t, %1; cvt.u32.u64 %0, t; }"
        : "=r"(a) : "l"(p));
    return a;
}

// packed fp32x2 FMA: full-rate FMA path on sm_103a (3-reg FFMA is half rate)
__device__ __forceinline__ void ffma2(unsigned long long& acc,
                                      unsigned long long a,
                                      unsigned long long b) {
    asm("fma.rn.f32x2 %0, %1, %2, %0;" : "+l"(acc) : "l"(a), "l"(b));
}
__device__ __forceinline__ unsigned long long pack2(float lo, float hi) {
    unsigned long long r;
    asm("mov.b64 %0, {%1, %2};" : "=l"(r) : "f"(lo), "f"(hi));
    return r;
}
__device__ __forceinline__ float2 unpack2(unsigned long long v) {
    float2 r;
    asm("mov.b64 {%0, %1}, %2;" : "=f"(r.x), "=f"(r.y) : "l"(v));
    return r;
}

// tanh(x) = 1 - 2/(exp(2x)+1), via MUFU.EX2 + MUFU.RCP. Abs err ~1e-7.
__device__ __forceinline__ float fast_tanh(float x) {
    float e, r;
    float t = x * 2.8853900817779268f;      // 2*log2(e)
    asm("ex2.approx.f32 %0, %1;" : "=f"(e) : "f"(t));
    float d = e + 1.0f;
    asm("rcp.approx.f32 %0, %1;" : "=f"(r) : "f"(d));
    return fmaf(-2.0f, r, 1.0f);
}

// ---------------------------------------------------------------------------
// Scan kernel: cluster of 2 CTAs per batch element.
//   CTA rank r owns output columns j in [128r, 128r+128).
//   256 threads: jj = tid&127 (output col), q = tid>>7.
//   k-half assignment (R10 change): q0 threads consume the LOCALLY produced
//   h half (no remote dependency), q1 threads consume the PEER half.
//   Only q1 warps wait on the mbarrier -> the q0 dot overlaps DSMEM flight.
//   Exchange: ONE 512B cp.async.bulk (smem->peer smem, complete_tx fused)
//   per CTA per step, replacing R7's 128 per-lane st.async transactions.
//   Two alternating mbarriers (one per parity) make the expect_tx posting
//   race-free while the previous phase is still pending.
// ---------------------------------------------------------------------------
__global__ void __cluster_dims__(2, 1, 1) __launch_bounds__(256, 1)
scan_kernel(const float* __restrict__ A)
{
    __shared__ __align__(16) float h_s[2][H_DIM];   // double-buffered state
    __shared__ float scratch[128];                  // pair-reduce partials
    __shared__ __align__(8) unsigned long long mbar[2];  // per-parity barriers

    const int tid   = threadIdx.x;
    const int jj    = tid & 127;
    const int q     = tid >> 7;            // 0 or 1
    uint32_t rank;
    asm("mov.u32 %0, %%cluster_ctarank;" : "=r"(rank));
    const int b     = blockIdx.x >> 1;
    const int j     = (int)rank * 128 + jj;            // global output column
    // q0 -> local half (rank*128), q1 -> peer half
    const int kbase = (int)(((q + rank) & 1u) * 128);

    // --- A slice -> registers, packed as (A[k][j], A[k+1][j]) pairs --------
    unsigned long long Ar[64];
#pragma unroll
    for (int m = 0; m < 64; m++) {
        float a0 = A[(size_t)(kbase + 2 * m)     * H_DIM + j];
        float a1 = A[(size_t)(kbase + 2 * m + 1) * H_DIM + j];
        Ar[m] = pack2(a0, a1);
    }

    // --- init shared state + mbarriers --------------------------------------
    h_s[0][tid] = 0.0f;          // tid covers 0..255 == H_DIM
    h_s[1][tid] = 0.0f;
    uint32_t mbar_a = smem_u32(mbar);
    if (tid == 0) {
        asm volatile("mbarrier.init.shared.b64 [%0], %1;"
                     :: "r"(mbar_a),      "r"(1u) : "memory");
        asm volatile("mbarrier.init.shared.b64 [%0], %1;"
                     :: "r"(mbar_a + 8u), "r"(1u) : "memory");
    }
    // cluster-wide visibility of init/zeros before any remote traffic
    asm volatile("barrier.cluster.arrive.aligned;" ::: "memory");
    asm volatile("barrier.cluster.wait.aligned;"   ::: "memory");

    // --- peer addresses (DSMEM) --------------------------------------------
    uint32_t peer = rank ^ 1u;
    uint32_t h0_a = smem_u32(&h_s[0][0]);
    uint32_t peer_h0, peer_mbar;
    asm("mapa.shared::cluster.u32 %0, %1, %2;" : "=r"(peer_h0)   : "r"(h0_a),   "r"(peer));
    asm("mapa.shared::cluster.u32 %0, %1, %2;" : "=r"(peer_mbar) : "r"(mbar_a), "r"(peer));

    // --- xB prefetch pipeline (distance 2 hides DRAM latency) ---------------
    const float* xb_base = g_xB + ((size_t)b * T_LEN) * H_DIM + j;
    float*       hs_out  = g_hs + ((size_t)b * T_LEN) * H_DIM + j;
    float xb_pre[2] = {0.0f, 0.0f};
    if (q == 0) {
        xb_pre[0] = __ldg(xb_base);
        xb_pre[1] = __ldg(xb_base + H_DIM);
    }

    const uint32_t my_half_off = (uint32_t)rank * 512u;   // bytes within a row

    // --- main scan loop -----------------------------------------------------
    for (int t = 0; t < T_LEN; t++) {
        const int cur = t & 1;
        const int nxt = cur ^ 1;

        // post the expected-tx for THIS step's incoming peer data (phase t,
        // object t&1). Object t&1's previous use (phase t-2) completed at
        // iteration t-1's wait, so this post is race-free.
        if (tid == 0) {
            asm volatile("mbarrier.arrive.expect_tx.shared::cta.b64 _, [%0], %1;"
                         :: "r"(mbar_a + (uint32_t)cur * 8u), "r"(512u)
                         : "memory");
        }

        // q1 consumes the peer half of h_s[cur]: wait for phase t-1
        // (object (t-1)&1 = nxt, use index (t-1)>>1, parity ((t-1)>>1)&1).
        if (q == 1 && t > 0) {
            uint32_t par = (uint32_t)(((t - 1) >> 1) & 1);
            uint32_t wa  = mbar_a + (uint32_t)nxt * 8u;
            asm volatile(
                "{\n\t.reg .pred P;\n"
                "W%=:\n\t"
                "mbarrier.try_wait.parity.acquire.cta.shared::cta.b64 P, [%0], %1, 0x989680;\n\t"
                "@!P bra W%=;\n\t"
                "}"
                :: "r"(wa), "r"(par) : "memory");
        }

        // dot over my 128 k values (4 accumulators: chain 64 cyc, not 128)
        const ulonglong2* h2 =
            reinterpret_cast<const ulonglong2*>(&h_s[cur][kbase]);
        unsigned long long acc0 = 0ull, acc1 = 0ull, acc2 = 0ull, acc3 = 0ull;
#pragma unroll
        for (int m = 0; m < 16; m++) {
            ulonglong2 hv0 = h2[2 * m];
            ulonglong2 hv1 = h2[2 * m + 1];
            ffma2(acc0, hv0.x, Ar[4 * m]);
            ffma2(acc1, hv0.y, Ar[4 * m + 1]);
            ffma2(acc2, hv1.x, Ar[4 * m + 2]);
            ffma2(acc3, hv1.y, Ar[4 * m + 3]);
        }
        float2 u0 = unpack2(acc0), u1 = unpack2(acc1);
        float2 u2 = unpack2(acc2), u3 = unpack2(acc3);
        float partial = ((u0.x + u0.y) + (u1.x + u1.y)) +
                        ((u2.x + u2.y) + (u3.x + u3.y));

        if (q == 1) scratch[jj] = partial;
        __syncthreads();

        if (q == 0) {
            float tot = partial + scratch[jj] + xb_pre[t & 1];
            if (t + 2 < T_LEN)   // refill prefetch slot
                xb_pre[t & 1] = __ldg(xb_base + (size_t)(t + 2) * H_DIM);
            float hv = fast_tanh(tot);

            h_s[nxt][j] = hv;                   // local copy (my half)
            hs_out[(size_t)t * H_DIM] = hv;     // for out-GEMM
        }
        __syncthreads();   // my half of h_s[nxt] complete

        // ONE bulk DSMEM copy: my 512B half -> peer's h_s[nxt], credit the
        // peer's phase-t barrier (object t&1) via fused complete_tx.
        if (tid == 0 && t + 1 < T_LEN) {
            uint32_t row  = (uint32_t)nxt * (H_DIM * 4u);
            uint32_t src  = h0_a    + row + my_half_off;
            uint32_t dst  = peer_h0 + row + my_half_off;
            uint32_t pmb  = peer_mbar + (uint32_t)cur * 8u;
            asm volatile("fence.proxy.async.shared::cta;" ::: "memory");
            asm volatile(
                "cp.async.bulk.shared::cluster.shared::cta.mbarrier::complete_tx::bytes "
                "[%0], [%1], %2, [%3];"
                :: "r"(dst), "r"(src), "r"(512u), "r"(pmb)
                : "memory");
        }
    }

    asm volatile("barrier.cluster.arrive.aligned;" ::: "memory");
    asm volatile("barrier.cluster.wait.aligned;"   ::: "memory");
}

// ---------------------------------------------------------------------------
// fp32 tiled GEMM: C[M,N] = A[M,K] @ B[K,N], all row-major.
// 128x128 block tile, k-tile 16, 256 threads, 8x8 microtile, FFMA2 accums.
// (~90% of fp32 FMA roofline measured; unchanged.)
// ---------------------------------------------------------------------------
__global__ void __launch_bounds__(256)
gemm_f32(const float* __restrict__ Ag, const float* __restrict__ Bg,
         float* __restrict__ Cg, int M, int N, int K)
{
    __shared__ __align__(16) float As[16][128];   // transposed A tile
    __shared__ __align__(16) float Bs[16][128];

    const int tid = threadIdx.x;
    const int bm  = blockIdx.x * 128;
    const int bn  = blockIdx.y * 128;
    const int tx  = tid & 15;     // n direction
    const int ty  = tid >> 4;     // m direction
    const int m0  = ty * 8;
    const int n0  = tx * 8;

    unsigned long long acc[8][4];
#pragma unroll
    for (int i = 0; i < 8; i++)
#pragma unroll
        for (int p = 0; p < 4; p++) acc[i][p] = 0ull;

    for (int k0 = 0; k0 < K; k0 += 16) {
#pragma unroll
        for (int l = 0; l < 2; l++) {
            int v  = tid + l * 256;
            int r  = v >> 2;
            int c4 = v & 3;
            float4 a = *reinterpret_cast<const float4*>(
                &Ag[(size_t)(bm + r) * K + k0 + c4 * 4]);
            As[c4 * 4 + 0][r] = a.x;
            As[c4 * 4 + 1][r] = a.y;
            As[c4 * 4 + 2][r] = a.z;
            As[c4 * 4 + 3][r] = a.w;
        }
#pragma unroll
        for (int l = 0; l < 2; l++) {
            int v  = tid + l * 256;
            int kk = v >> 5;
            int c4 = v & 31;
            *reinterpret_cast<float4*>(&Bs[kk][c4 * 4]) =
                *reinterpret_cast<const float4*>(
                    &Bg[(size_t)(k0 + kk) * N + bn + c4 * 4]);
        }
        __syncthreads();

#pragma unroll
        for (int kk = 0; kk < 16; kk++) {
            float4 a0 = *reinterpret_cast<const float4*>(&As[kk][m0]);
            float4 a1 = *reinterpret_cast<const float4*>(&As[kk][m0 + 4]);
            ulonglong2 b0 = *reinterpret_cast<const ulonglong2*>(&Bs[kk][n0]);
            ulonglong2 b1 = *reinterpret_cast<const ulonglong2*>(&Bs[kk][n0 + 4]);

            unsigned long long ap[8];
            ap[0] = pack2(a0.x, a0.x); ap[1] = pack2(a0.y, a0.y);
            ap[2] = pack2(a0.z, a0.z); ap[3] = pack2(a0.w, a0.w);
            ap[4] = pack2(a1.x, a1.x); ap[5] = pack2(a1.y, a1.y);
            ap[6] = pack2(a1.z, a1.z); ap[7] = pack2(a1.w, a1.w);
            unsigned long long bv0 = b0.x, bv1 = b0.y, bv2 = b1.x, bv3 = b1.y;

#pragma unroll
            for (int i = 0; i < 8; i++) {
                ffma2(acc[i][0], ap[i], bv0);
                ffma2(acc[i][1], ap[i], bv1);
                ffma2(acc[i][2], ap[i], bv2);
                ffma2(acc[i][3], ap[i], bv3);
            }
        }
        __syncthreads();
    }

#pragma unroll
    for (int i = 0; i < 8; i++) {
        float o[8];
#pragma unroll
        for (int p = 0; p < 4; p++) {
            float2 u = unpack2(acc[i][p]);
            o[2 * p] = u.x; o[2 * p + 1] = u.y;
        }
        float4* dst = reinterpret_cast<float4*>(
            &Cg[(size_t)(bm + m0 + i) * N + bn + n0]);
        dst[0] = make_float4(o[0], o[1], o[2], o[3]);
        dst[1] = make_float4(o[4], o[5], o[6], o[7]);
    }
}

// ---------------------------------------------------------------------------
// launch
// ---------------------------------------------------------------------------
extern "C" void kernel_launch(void* const* d_in, const int* in_sizes, int n_in,
                              void* d_out, int out_size)
{
    (void)in_sizes; (void)n_in; (void)out_size;
    const float* x  = (const float*)d_in[0];   // [32, 2048, 128]
    const float* A  = (const float*)d_in[1];   // [256, 256]
    const float* Bm = (const float*)d_in[2];   // [128, 256]
    const float* C  = (const float*)d_in[3];   // [256, 256]
    float* out = (float*)d_out;                // [32, 2048, 256]

    float* xB = nullptr;
    float* hs = nullptr;
    cudaGetSymbolAddress((void**)&xB, g_xB);   // pure query: capture-safe
    cudaGetSymbolAddress((void**)&hs, g_hs);

    const int M = B_SZ * T_LEN;                // 65536

    // 1) xB = x @ Bm   (M x 128) @ (128 x 256)
    gemm_f32<<<dim3(M / 128, H_DIM / 128), 256>>>(x, Bm, xB, M, H_DIM, I_DIM);
    // 2) sequential tanh scan, 32 clusters of 2 CTAs
    scan_kernel<<<B_SZ * 2, 256>>>(A);
    // 3) out = hs @ C  (M x 256) @ (256 x 256)
    gemm_f32<<<dim3(M / 128, H_DIM / 128), 256>>>(hs, C, out, M, H_DIM, H_DIM);
}